// round 16
// baseline (speedup 1.0000x reference)
#include <cuda_runtime.h>
#include <cstdint>

// Correlation D=4 via mma.sync m16n8k8 tf32 (base PTX, legal on compute_103).
//
// R15-proven math/indexing. CHANGE: tf32 conversion moved to FILL time.
// Fill = LDG.128 -> cvt.rna.tf32 x4 -> STS.128 (smem holds tf32 bit patterns),
// 2-buffer ring, LDG(s+1) issued before compute(s) to hide DRAM latency.
// Inner loop is now pure LDS.32 -> MMA (no per-read CVT: shorter dep chain,
// ~25% fewer issue slots, frees registers for load hoisting).
//
// CTA: 8h x 32w = 256 px, 512 thr = 16 warps; warp = 2h x 8w m-tile.
// D[m=(il,wl)][n=(r,cc)] over K=128 ch; N = 10 r x 16 cc = 20 n-blocks.
// out[n,ky*9+kx,h0+2ip+il,w0+8wgp+wl] = D[il*8+wl][(il+ky)*40-ish band]/128.
// smem: x1 [c][8*32]+8pad (c-stride 264), x2 [rg*8+c][40] -> conflict-free.

#define HW_ 65536
#define C_ 128
#define CB 8
#define NSTAGE 16
#define X1CH 2112                // x1 floats/chunk: 8 ch * 264
#define X2CH 5120                // x2 floats/chunk: 16 r * 8 ch * 40
#define BUFF (X1CH + X2CH)       // 7232 floats
#define BUFB (BUFF*4)            // 28928 B
#define SM_D (2*BUFB)            // 57856 B : epilogue D region starts here
#define SMEM_BYTES (SM_D + 16*272*4)   // +17408 = 75264 B
#define CSTRIDE (CB*HW_)
#define NTHREADS 512
#define NTASKS 1792              // 1280 x2 + 512 x1 float4 tasks / chunk

__device__ __forceinline__ uint32_t tf32c(float x) {
    uint32_t r;
    asm("cvt.rna.tf32.f32 %0, %1;" : "=r"(r) : "f"(x));
    return r;
}

__global__ void __launch_bounds__(NTHREADS, 1)
corr_mma_kernel(const float* __restrict__ x1, const float* __restrict__ x2,
                float* __restrict__ out) {
    extern __shared__ float sm[];
    const uint32_t smem_u = (uint32_t)__cvta_generic_to_shared(sm);
    const int tid  = threadIdx.x;
    const int lane = tid & 31;
    const int wq   = tid >> 5;      // 0..15
    const int ip   = wq >> 2;       // i-pair: rows h0+2ip, h0+2ip+1
    const int wgp  = wq & 3;        // w-group: cols w0+8wgp..+7
    const int g    = lane >> 2;     // groupID
    const int kq   = lane & 3;      // threadID_in_group

    const int bx = blockIdx.x;
    const int w0 = (bx & 7) * 32;
    const int h0 = ((bx >> 3) & 31) * 8;
    const int n  = bx >> 8;
    const float* x1n = x1 + (size_t)n * C_ * HW_;
    const float* x2n = x2 + (size_t)n * C_ * HW_;

    // ---------- loader: fixed per-thread slots (computed once) ----------
    // t < 1280 : x2 halo  [rg 0..15][c 0..7][q 0..9]  (zero at borders)
    // t >= 1280: x1 tile  [c 0..7][row 0..7][q 0..7]
    const float* lsrc[4];
    uint32_t     ldst[4];
    int          lok[4];
    #pragma unroll
    for (int k = 0; k < 4; ++k) {
        const int t = tid + k * NTHREADS;
        if (t < NTASKS) {
            if (t < 1280) {
                const int rg = t / 80, rem = t % 80;
                const int c = rem / 10, q = rem % 10;
                const int h  = h0 - 4 + rg;
                const int gw = w0 - 4 + q * 4;
                const bool ok = ((unsigned)h < 256u) && (gw >= 0) && (gw <= 252);
                lsrc[k] = x2n + (size_t)c * HW_ + (ok ? ((size_t)h * 256 + gw) : 0);
                ldst[k] = smem_u + (uint32_t)(X1CH + (rg * 8 + c) * 40 + q * 4) * 4u;
                lok[k]  = ok ? 1 : 0;
            } else {
                const int t2 = t - 1280;
                const int c = t2 / 64, rem = t2 % 64;
                const int row = rem / 8, q = rem % 8;
                lsrc[k] = x1n + (size_t)c * HW_ + (size_t)(h0 + row) * 256 + w0 + q * 4;
                ldst[k] = smem_u + (uint32_t)(c * 264 + row * 32 + q * 4) * 4u;
                lok[k]  = 1;
            }
        } else { lsrc[k] = x1n; ldst[k] = smem_u; lok[k] = -1; }
    }
    const bool has4 = (lok[3] >= 0);   // tid < 256

    uint32_t rr[4][4];   // staging registers (tf32 bit patterns)

    auto load_regs = [&]() {
        #pragma unroll
        for (int k = 0; k < 4; ++k) {
            if (k < 3 || has4) {
                float4 v = make_float4(0.f, 0.f, 0.f, 0.f);
                if (lok[k]) v = *reinterpret_cast<const float4*>(lsrc[k]);
                rr[k][0] = tf32c(v.x); rr[k][1] = tf32c(v.y);
                rr[k][2] = tf32c(v.z); rr[k][3] = tf32c(v.w);
                lsrc[k] += CSTRIDE;
            }
        }
    };
    auto sts_regs = [&](int buf) {
        const uint32_t base = buf * BUFB;
        #pragma unroll
        for (int k = 0; k < 4; ++k) {
            if (k < 3 || has4) {
                asm volatile("st.shared.v4.b32 [%0], {%1,%2,%3,%4};"
                             :: "r"(ldst[k] + base),
                                "r"(rr[k][0]), "r"(rr[k][1]),
                                "r"(rr[k][2]), "r"(rr[k][3]) : "memory");
            }
        }
    };

    // ---------- fragment offsets (floats, buffer-relative) ----------
    const int a0off = kq * 264 + ip * 64 + wgp * 8 + g;
    const int bbase = X1CH + (ip * 16 + kq) * 40 + wgp * 8 + g;

    float acc[20][4];
    #pragma unroll
    for (int i = 0; i < 20; ++i)
        #pragma unroll
        for (int j = 0; j < 4; ++j) acc[i][j] = 0.0f;

    const uint32_t* smu = reinterpret_cast<const uint32_t*>(sm);

    auto compute_stage = [&](int buf) {
        const uint32_t* bp = smu + buf * BUFF;
        const uint32_t A0 = bp[a0off];
        const uint32_t A1 = bp[a0off + 32];
        const uint32_t A2 = bp[a0off + 1056];
        const uint32_t A3 = bp[a0off + 1088];
        #pragma unroll
        for (int r = 0; r < 10; ++r) {
            #pragma unroll
            for (int cb = 0; cb < 2; ++cb) {
                const int o = bbase + r * 320 + cb * 8;
                const uint32_t B0 = bp[o];
                const uint32_t B1 = bp[o + 160];
                float* c = acc[r * 2 + cb];
                asm volatile(
                    "mma.sync.aligned.m16n8k8.row.col.f32.tf32.tf32.f32 "
                    "{%0,%1,%2,%3}, {%4,%5,%6,%7}, {%8,%9}, {%0,%1,%2,%3};"
                    : "+f"(c[0]), "+f"(c[1]), "+f"(c[2]), "+f"(c[3])
                    : "r"(A0), "r"(A1), "r"(A2), "r"(A3), "r"(B0), "r"(B1));
            }
        }
    };

    // ---------- 2-buffer LDG->CVT->STS pipeline ----------
    // iter s: [barrier] LDG(s+1) ; compute(s) ; STS(s+1) ; barrier-at-top.
    // WAR safe: STS(s+1) writes buf (s+1)&1, last read by compute(s-1),
    // which completed before the barrier that preceded compute(s).
    load_regs();        // stage 0
    sts_regs(0);
    __syncthreads();

    #pragma unroll 1
    for (int s = 0; s < NSTAGE; ++s) {
        if (s < NSTAGE - 1) load_regs();           // stage s+1 (DRAM latency
        compute_stage(s & 1);                      //  hidden under compute)
        if (s < NSTAGE - 1) {
            sts_regs((s + 1) & 1);
            __syncthreads();
        }
    }

    // ---------- epilogue: per-warp D dump + band extraction (R15-proven) ----
    float* dbase = sm + (SM_D / 4) + wq * 272;    // [16][17] floats per warp
    const float inv = 1.0f / 128.0f;
    #pragma unroll 1
    for (int r = 0; r < 10; ++r) {
        #pragma unroll
        for (int cb = 0; cb < 2; ++cb) {
            const float* c = acc[r * 2 + cb];
            const int ccb = cb * 8 + 2 * kq;
            dbase[g * 17 + ccb]           = c[0];
            dbase[g * 17 + ccb + 1]       = c[1];
            dbase[(g + 8) * 17 + ccb]     = c[2];
            dbase[(g + 8) * 17 + ccb + 1] = c[3];
        }
        __syncwarp();
        #pragma unroll
        for (int il = 0; il < 2; ++il) {
            const int ky = r - il;
            if (ky >= 0 && ky < 9) {
                float* op = out + ((size_t)(n * 81 + ky * 9) * HW_)
                                + (size_t)(h0 + 2 * ip + il) * 256 + w0 + wgp * 8;
                #pragma unroll
                for (int t0 = 0; t0 < 3; ++t0) {
                    const int t = lane + t0 * 32;
                    if (t < 72) {
                        const int kx = t >> 3, wl = t & 7;
                        op[(size_t)kx * HW_ + wl] =
                            dbase[(il * 8 + wl) * 17 + wl + kx] * inv;
                    }
                }
            }
        }
        __syncwarp();
    }
}

extern "C" void kernel_launch(void* const* d_in, const int* in_sizes, int n_in,
                              void* d_out, int out_size) {
    const float* x1 = (const float*)d_in[0];
    const float* x2 = (const float*)d_in[1];
    float* out = (float*)d_out;

    cudaFuncSetAttribute(corr_mma_kernel, cudaFuncAttributeMaxDynamicSharedMemorySize,
                         SMEM_BYTES);

    dim3 block(NTHREADS, 1, 1);   // 512 threads = 16 warps
    dim3 grid(1024, 1, 1);        // 8 w-tiles x 32 h-tiles x 4 n
    corr_mma_kernel<<<grid, block, SMEM_BYTES>>>(x1, x2, out);
}

// round 17
// speedup vs baseline: 1.1267x; 1.1267x over previous
#include <cuda_runtime.h>
#include <cstdint>

// Correlation D=4 via mma.sync m16n8k8 tf32 (base PTX, legal on compute_103).
//
// R15-proven math with the r-dimension SPLIT ACROSS WARPS: each output
// (il,ky) reads D at exactly one band row r=il+ky, so no reduction couples
// different r -> two warps share an m-tile, one takes r 0-4, other r 5-9.
// Accumulators/thread: 80 -> 40, enabling 3 CTAs/SM (24 warps, was 16).
//
// CTA: 2h x 32w = 64 px, 256 thr = 8 warps = 4 m-tiles x 2 r-halves.
// Warp m-tile: m16 = 2 h-rows x 8 w.  N = 5 r x 16 cc = 10 n-blocks.
// smem: x1 [c][row*32] c-stride 72 (=8 mod 32), x2 [r*8+c][40] (=8 mod 32)
// -> all fragment LDS conflict-free (R15-verified pattern, ip=0).
// cp.async 3-buffer ring (R8-proven accounting), CB=8, per-read cvt.rna.tf32.

#define HW_ 65536
#define C_ 128
#define CB 8
#define NSTAGE 16
#define X1CH 576                 // x1 floats/chunk: 8 ch * 72
#define X2CH 3200                // x2 floats/chunk: 10 r * 8 ch * 40
#define BUFF (X1CH + X2CH)       // 3776 floats
#define BUFB (BUFF*4)            // 15104 B
#define SM_D (3*BUFB)            // 45312 B : epilogue D region
#define SMEM_BYTES (SM_D + 8*272*4)    // +8704 = 54016 B
#define CSTRIDE (CB*HW_)
#define NTHREADS 256
#define NTASKS 928               // 800 x2 + 128 x1 float4 tasks / chunk

__device__ __forceinline__ void cp_async16(uint32_t dst, const float* src, int sz) {
    asm volatile("cp.async.cg.shared.global [%0], [%1], 16, %2;\n"
                 :: "r"(dst), "l"(src), "r"(sz) : "memory");
}
__device__ __forceinline__ void cp_commit() {
    asm volatile("cp.async.commit_group;\n" ::: "memory");
}
__device__ __forceinline__ uint32_t tf32c(float x) {
    uint32_t r;
    asm("cvt.rna.tf32.f32 %0, %1;" : "=r"(r) : "f"(x));
    return r;
}

__global__ void __launch_bounds__(NTHREADS, 3)
corr_mma_kernel(const float* __restrict__ x1, const float* __restrict__ x2,
                float* __restrict__ out) {
    extern __shared__ float sm[];
    const uint32_t smem_u = (uint32_t)__cvta_generic_to_shared(sm);
    const int tid  = threadIdx.x;
    const int lane = tid & 31;
    const int wq   = tid >> 5;      // 0..7
    const int wgp  = wq >> 1;       // 0..3 : w-group (cols w0+8wgp..+7)
    const int rh   = (wq & 1) * 5;  // r-half: rows 0-4 or 5-9 of the band
    const int g    = lane >> 2;     // groupID
    const int kq   = lane & 3;      // threadID_in_group

    const int bx = blockIdx.x;
    const int w0 = (bx & 7) * 32;
    const int h0 = ((bx >> 3) & 127) * 2;
    const int n  = bx >> 10;
    const float* x1n = x1 + (size_t)n * C_ * HW_;
    const float* x2n = x2 + (size_t)n * C_ * HW_;

    // ---------- loader: fixed per-thread slots (computed once) ----------
    // t < 800 : x2 halo  [rg 0..9][c 0..7][q 0..9]  (zfill at borders)
    // t >= 800: x1 tile  [c 0..7][row 0..1][q 0..7]
    const float* lsrc[4];
    uint32_t     ldst[4];
    int          lsz[4];
    #pragma unroll
    for (int k = 0; k < 4; ++k) {
        const int t = tid + k * NTHREADS;
        if (t < NTASKS) {
            if (t < 800) {
                const int rg = t / 80, rem = t % 80;
                const int c = rem / 10, q = rem % 10;
                const int h  = h0 - 4 + rg;
                const int gw = w0 - 4 + q * 4;
                const bool ok = ((unsigned)h < 256u) && (gw >= 0) && (gw <= 252);
                lsrc[k] = x2n + (size_t)c * HW_ + (ok ? ((size_t)h * 256 + gw) : 0);
                ldst[k] = smem_u + (uint32_t)(X1CH + (rg * 8 + c) * 40 + q * 4) * 4u;
                lsz[k]  = ok ? 16 : 0;
            } else {
                const int t2 = t - 800;
                const int c = t2 >> 4, rem = t2 & 15;
                const int row = rem >> 3, q = rem & 7;
                lsrc[k] = x1n + (size_t)c * HW_ + (size_t)(h0 + row) * 256 + w0 + q * 4;
                ldst[k] = smem_u + (uint32_t)(c * 72 + row * 32 + q * 4) * 4u;
                lsz[k]  = 16;
            }
        } else { lsrc[k] = x1n; ldst[k] = smem_u; lsz[k] = -1; }
    }
    const bool has4 = (lsz[3] >= 0);   // tid < 160

    auto load_stage = [&](int buf) {
        const uint32_t base = buf * BUFB;
        cp_async16(ldst[0] + base, lsrc[0], lsz[0]);
        cp_async16(ldst[1] + base, lsrc[1], lsz[1]);
        cp_async16(ldst[2] + base, lsrc[2], lsz[2]);
        if (has4) cp_async16(ldst[3] + base, lsrc[3], lsz[3] < 0 ? 0 : lsz[3]);
        cp_commit();
        lsrc[0] += CSTRIDE; lsrc[1] += CSTRIDE; lsrc[2] += CSTRIDE; lsrc[3] += CSTRIDE;
    };

    // ---------- fragment offsets (floats, buffer-relative; R15 maps, ip=0) ----
    // A: a0<->(row g, k=kq), a1<->(row g+8 -> il=1), a2/a3: k+4
    const int a0off = kq * 72 + wgp * 8 + g;
    // B block (r,cb): rg=r, c=kq (B1: c=kq+4), cc = wgp*8 + cb*8 + g
    const int bbase = X1CH + (rh * 8 + kq) * 40 + wgp * 8 + g;

    float acc[10][4];
    #pragma unroll
    for (int i = 0; i < 10; ++i)
        #pragma unroll
        for (int j = 0; j < 4; ++j) acc[i][j] = 0.0f;

    auto compute_stage = [&](int buf) {
        const float* bp = sm + buf * BUFF;
        const uint32_t A0 = tf32c(bp[a0off]);
        const uint32_t A1 = tf32c(bp[a0off + 32]);
        const uint32_t A2 = tf32c(bp[a0off + 288]);
        const uint32_t A3 = tf32c(bp[a0off + 320]);
        #pragma unroll
        for (int rr = 0; rr < 5; ++rr) {
            #pragma unroll
            for (int cb = 0; cb < 2; ++cb) {
                const int o = bbase + rr * 320 + cb * 8;
                const uint32_t B0 = tf32c(bp[o]);
                const uint32_t B1 = tf32c(bp[o + 160]);
                float* c = acc[rr * 2 + cb];
                asm volatile(
                    "mma.sync.aligned.m16n8k8.row.col.f32.tf32.tf32.f32 "
                    "{%0,%1,%2,%3}, {%4,%5,%6,%7}, {%8,%9}, {%0,%1,%2,%3};"
                    : "+f"(c[0]), "+f"(c[1]), "+f"(c[2]), "+f"(c[3])
                    : "r"(A0), "r"(A1), "r"(A2), "r"(A3), "r"(B0), "r"(B1));
            }
        }
    };

    // ---------- 3-buffer cp.async ring (R8/R15-proven accounting) ----------
    load_stage(0);
    load_stage(1);
    int bufl = 2, bufc = 0;
    #pragma unroll 1
    for (int s = 0; s < NSTAGE; ++s) {
        if (s < NSTAGE - 1) asm volatile("cp.async.wait_group 1;\n" ::: "memory");
        else                asm volatile("cp.async.wait_group 0;\n" ::: "memory");
        __syncthreads();
        if (s < NSTAGE - 2) {
            load_stage(bufl);
            bufl = (bufl == 2) ? 0 : bufl + 1;
        }
        compute_stage(bufc);
        bufc = (bufc == 2) ? 0 : bufc + 1;
    }

    // ---------- epilogue: per-warp D dump + band extraction (R15-proven) ----
    float* dbase = sm + (SM_D / 4) + wq * 272;    // [16][17] floats per warp
    const float inv = 1.0f / 128.0f;
    #pragma unroll 1
    for (int rr = 0; rr < 5; ++rr) {
        const int r = rh + rr;
        #pragma unroll
        for (int cb = 0; cb < 2; ++cb) {
            const float* c = acc[rr * 2 + cb];
            const int ccb = cb * 8 + 2 * kq;
            dbase[g * 17 + ccb]           = c[0];
            dbase[g * 17 + ccb + 1]       = c[1];
            dbase[(g + 8) * 17 + ccb]     = c[2];
            dbase[(g + 8) * 17 + ccb + 1] = c[3];
        }
        __syncwarp();
        #pragma unroll
        for (int il = 0; il < 2; ++il) {
            const int ky = r - il;
            if (ky >= 0 && ky < 9) {
                float* op = out + ((size_t)(n * 81 + ky * 9) * HW_)
                                + (size_t)(h0 + il) * 256 + w0 + wgp * 8;
                #pragma unroll
                for (int t0 = 0; t0 < 3; ++t0) {
                    const int t = lane + t0 * 32;
                    if (t < 72) {
                        const int kx = t >> 3, wl = t & 7;
                        op[(size_t)kx * HW_ + wl] =
                            dbase[(il * 8 + wl) * 17 + wl + kx] * inv;
                    }
                }
            }
        }
        __syncwarp();
    }
}

extern "C" void kernel_launch(void* const* d_in, const int* in_sizes, int n_in,
                              void* d_out, int out_size) {
    const float* x1 = (const float*)d_in[0];
    const float* x2 = (const float*)d_in[1];
    float* out = (float*)d_out;

    cudaFuncSetAttribute(corr_mma_kernel, cudaFuncAttributeMaxDynamicSharedMemorySize,
                         SMEM_BYTES);

    dim3 block(NTHREADS, 1, 1);   // 256 threads = 8 warps
    dim3 grid(4096, 1, 1);        // 8 w-tiles x 128 h-strips x 4 n
    corr_mma_kernel<<<grid, block, SMEM_BYTES>>>(x1, x2, out);
}